// round 1
// baseline (speedup 1.0000x reference)
#include <cuda_runtime.h>
#include <math.h>

#define T_STEPS 128
#define BATCH   256
#define DIN     256
#define DH      1024
#define DOUT    256

// Scratch: Z = xs@W1x + b1 for all timesteps, plus ping-pong h buffers.
__device__ float g_z[(size_t)T_STEPS * BATCH * DH];   // 134 MB
__device__ float g_h[2 * (size_t)BATCH * DH];         // 2 MB

// ---------------- packed f32x2 helpers (FFMA2 path) ----------------
__device__ __forceinline__ void fma2(unsigned long long& acc,
                                     unsigned long long a,
                                     unsigned long long b) {
    asm("fma.rn.f32x2 %0, %1, %2, %0;" : "+l"(acc) : "l"(a), "l"(b));
}
__device__ __forceinline__ unsigned long long pack2(float x, float y) {
    unsigned long long r;
    asm("mov.b64 %0, {%1, %2};" : "=l"(r) : "f"(x), "f"(y));
    return r;
}
__device__ __forceinline__ float2 unpack2(unsigned long long v) {
    float2 f;
    asm("mov.b64 {%0, %1}, %2;" : "=f"(f.x), "=f"(f.y) : "l"(v));
    return f;
}

// ---------------- zero-init kernel ----------------
__global__ void zero_kernel(float* __restrict__ p, int n) {
    int i = blockIdx.x * blockDim.x + threadIdx.x;
    if (i < n) p[i] = 0.0f;
}

// ---------------- generic tiled fp32x2 GEMM ----------------
// MODE 0: C = A@B + bias_vec[n]                (Z precompute, bias = b1)
// MODE 1: C = tanh(A@B + aux[m,n])             (RNN step, aux = Z slice, b1 already folded)
// MODE 2: C = A@B + aux[0]                     (readout, aux = b2 scalar ptr)
template <int BM, int BN, int BK, int TM, int MODE>
__global__ void __launch_bounds__(256)
gemm_f32x2(const float* __restrict__ A, const float* __restrict__ Bm,
           const float* __restrict__ aux, float* __restrict__ C,
           int M, int N, int K) {
    constexpr int TN = 4;                       // 2 f32x2 pairs per row
    constexpr int NT = (BM / TM) * (BN / TN);   // must be 256
    static_assert(NT == 256, "block must be 256 threads");
    constexpr int PADA = 4;

    __shared__ float As[BK][BM + PADA];         // k-major (transposed) A tile
    __shared__ float Bs[BK][BN];

    const int tid = threadIdx.x;
    const int n0 = blockIdx.x * BN;
    const int m0 = blockIdx.y * BM;

    constexpr int A_PER = (BM * BK / 4) / NT;   // float4 loads per thread
    constexpr int B_PER = (BK * BN / 4) / NT;

    float4 ar[A_PER], br[B_PER];

    auto loadA = [&](int kt) {
#pragma unroll
        for (int i = 0; i < A_PER; i++) {
            int idx = tid + i * NT;
            int row = idx / (BK / 4);
            int kc  = idx % (BK / 4);
            ar[i] = *reinterpret_cast<const float4*>(
                &A[(size_t)(m0 + row) * K + kt * BK + kc * 4]);
        }
    };
    auto storeA = [&]() {
#pragma unroll
        for (int i = 0; i < A_PER; i++) {
            int idx = tid + i * NT;
            int row = idx / (BK / 4);
            int kc  = idx % (BK / 4);
            As[kc * 4 + 0][row] = ar[i].x;
            As[kc * 4 + 1][row] = ar[i].y;
            As[kc * 4 + 2][row] = ar[i].z;
            As[kc * 4 + 3][row] = ar[i].w;
        }
    };
    auto loadB = [&](int kt) {
#pragma unroll
        for (int i = 0; i < B_PER; i++) {
            int idx = tid + i * NT;
            int kr = idx / (BN / 4);
            int nc = idx % (BN / 4);
            br[i] = *reinterpret_cast<const float4*>(
                &Bm[(size_t)(kt * BK + kr) * N + n0 + nc * 4]);
        }
    };
    auto storeB = [&]() {
#pragma unroll
        for (int i = 0; i < B_PER; i++) {
            int idx = tid + i * NT;
            int kr = idx / (BN / 4);
            int nc = idx % (BN / 4);
            *reinterpret_cast<float4*>(&Bs[kr][nc * 4]) = br[i];
        }
    };

    unsigned long long acc[TM][2];
#pragma unroll
    for (int i = 0; i < TM; i++) {
        acc[i][0] = pack2(0.0f, 0.0f);
        acc[i][1] = pack2(0.0f, 0.0f);
    }

    const int rg = tid / (BN / TN);
    const int cg = tid % (BN / TN);
    const int r0 = rg * TM;
    const int c0 = cg * TN;

    const int nk = K / BK;
    loadA(0); loadB(0);
    storeA(); storeB();
    __syncthreads();

    for (int kt = 0; kt < nk; kt++) {
        if (kt + 1 < nk) { loadA(kt + 1); loadB(kt + 1); }  // reg prefetch
#pragma unroll
        for (int k = 0; k < BK; k++) {
            float a[TM];
            if (TM == 2) {
                float2 av = *reinterpret_cast<const float2*>(&As[k][r0]);
                a[0] = av.x; a[1] = av.y;
            } else {
                float4 av = *reinterpret_cast<const float4*>(&As[k][r0]);
                a[0] = av.x; a[1] = av.y; a[2] = av.z; a[3] = av.w;
            }
            float4 bv = *reinterpret_cast<const float4*>(&Bs[k][c0]);
            unsigned long long b01 = pack2(bv.x, bv.y);
            unsigned long long b23 = pack2(bv.z, bv.w);
#pragma unroll
            for (int i = 0; i < TM; i++) {
                unsigned long long aa = pack2(a[i], a[i]);
                fma2(acc[i][0], aa, b01);
                fma2(acc[i][1], aa, b23);
            }
        }
        __syncthreads();
        if (kt + 1 < nk) { storeA(); storeB(); __syncthreads(); }
    }

    // epilogue
#pragma unroll
    for (int i = 0; i < TM; i++) {
        float2 p0 = unpack2(acc[i][0]);
        float2 p1 = unpack2(acc[i][1]);
        float4 v = make_float4(p0.x, p0.y, p1.x, p1.y);
        const int row = m0 + r0 + i;
        const int col = n0 + c0;
        const size_t off = (size_t)row * N + col;
        if (MODE == 0) {
            float4 b = *reinterpret_cast<const float4*>(&aux[col]);
            v.x += b.x; v.y += b.y; v.z += b.z; v.w += b.w;
        } else if (MODE == 1) {
            float4 z = *reinterpret_cast<const float4*>(&aux[off]);
            v.x = tanhf(v.x + z.x);
            v.y = tanhf(v.y + z.y);
            v.z = tanhf(v.z + z.z);
            v.w = tanhf(v.w + z.w);
        } else {
            float s = aux[0];
            v.x += s; v.y += s; v.z += s; v.w += s;
        }
        *reinterpret_cast<float4*>(&C[off]) = v;
    }
}

extern "C" void kernel_launch(void* const* d_in, const int* in_sizes, int n_in,
                              void* d_out, int out_size) {
    const float* xs  = (const float*)d_in[0];  // [128,256,256]
    const float* W1x = (const float*)d_in[1];  // [256,1024]
    const float* W1h = (const float*)d_in[2];  // [1024,1024]
    const float* b1  = (const float*)d_in[3];  // [1024]
    const float* W2  = (const float*)d_in[4];  // [1024,256]
    const float* b2  = (const float*)d_in[5];  // scalar
    float* out = (float*)d_out;                // [256,256]

    float* zp = nullptr;
    float* hp = nullptr;
    cudaGetSymbolAddress((void**)&zp, g_z);
    cudaGetSymbolAddress((void**)&hp, g_h);
    float* h0 = hp;
    float* h1 = hp + (size_t)BATCH * DH;

    // h(-1) = 0
    {
        int n = BATCH * DH;
        zero_kernel<<<(n + 255) / 256, 256>>>(h0, n);
    }

    // Z[t,b,:] = xs[t,b,:] @ W1x + b1   (M = T*B = 32768, N = 1024, K = 256)
    gemm_f32x2<64, 64, 32, 4, 0>
        <<<dim3(DH / 64, (T_STEPS * BATCH) / 64), 256>>>(
            xs, W1x, b1, zp, T_STEPS * BATCH, DH, DIN);

    // Recurrence: h <- tanh(Z[t] + h @ W1h)
    for (int t = 0; t < T_STEPS; t++) {
        float* hc = (t & 1) ? h1 : h0;
        float* hn = (t & 1) ? h0 : h1;
        gemm_f32x2<32, 64, 32, 2, 1>
            <<<dim3(DH / 64, BATCH / 32), 256>>>(
                hc, W1h, zp + (size_t)t * BATCH * DH, hn, BATCH, DH, DH);
    }

    // out = h_final @ W2 + b2   (h_final lives in buffer 0 after 128 steps)
    gemm_f32x2<32, 64, 32, 2, 2>
        <<<dim3(DOUT / 64, BATCH / 32), 256>>>(
            h0, W2, b2, out, BATCH, DOUT, DH);
}